// round 7
// baseline (speedup 1.0000x reference)
#include <cuda_runtime.h>

#define N_USER   200000
#define N_ITEM   100000
#define N_NODES_ 300000
#define EMB      80
#define EMBV     20          // float4 chunks per row
#define FEAT     16
#define NNZ_     1000000
#define BATCH_   4096
#define NLAYER   3

typedef unsigned long long ull;

// ---------------- device scratch ----------------
static __device__ float g_E0[(size_t)N_NODES_ * EMB];   // 96 MB (ping)
static __device__ float g_E1[(size_t)N_NODES_ * EMB];   // 96 MB (pong)
static __device__ int   g_rowptr[N_NODES_ + 1];
static __device__ int   g_cnt[N_NODES_];
static __device__ int   g_bsum[1024];
static __device__ int   g_winner[N_USER];
static __device__ int   g_cols[NNZ_];
static __device__ float g_vals[NNZ_];

// ---------------- f32x2 helpers ----------------
__device__ __forceinline__ ull fma2(ull a, ull b, ull c) {
    ull d;
    asm("fma.rn.f32x2 %0, %1, %2, %3;" : "=l"(d) : "l"(a), "l"(b), "l"(c));
    return d;
}
__device__ __forceinline__ ull bcast2(float x) {
    ull d;
    asm("mov.b64 %0, {%1, %1};" : "=l"(d) : "f"(x));
    return d;
}
__device__ __forceinline__ float2 unpk(ull v) {
    float2 r;
    asm("mov.b64 {%0, %1}, %2;" : "=f"(r.x), "=f"(r.y) : "l"(v));
    return r;
}

// ---------------- CSR build ----------------
__global__ void k_init() {
    int i = blockIdx.x * blockDim.x + threadIdx.x;
    if (i < N_NODES_) g_cnt[i] = 0;
    if (i < N_USER)   g_winner[i] = -1;
}

__global__ void k_hist(const int* __restrict__ rows) {
    int i = blockIdx.x * blockDim.x + threadIdx.x;
    if (i < NNZ_) atomicAdd(&g_cnt[rows[i]], 1);
}

__global__ void k_scan1() {
    __shared__ int s[1024];
    int tid = threadIdx.x;
    int i = blockIdx.x * 1024 + tid;
    int v = (i < N_NODES_) ? g_cnt[i] : 0;
    s[tid] = v; __syncthreads();
    for (int off = 1; off < 1024; off <<= 1) {
        int t = (tid >= off) ? s[tid - off] : 0;
        __syncthreads();
        s[tid] += t;
        __syncthreads();
    }
    if (i < N_NODES_) g_rowptr[i] = s[tid] - v;
    if (tid == 1023) g_bsum[blockIdx.x] = s[1023];
}

__global__ void k_scan2(int nb) {
    __shared__ int s[1024];
    int tid = threadIdx.x;
    int v = (tid < nb) ? g_bsum[tid] : 0;
    s[tid] = v; __syncthreads();
    for (int off = 1; off < 1024; off <<= 1) {
        int t = (tid >= off) ? s[tid - off] : 0;
        __syncthreads();
        s[tid] += t;
        __syncthreads();
    }
    if (tid < nb) g_bsum[tid] = s[tid] - v;
}

__global__ void k_scan3() {
    int i = blockIdx.x * blockDim.x + threadIdx.x;
    if (i < N_NODES_) {
        int excl = g_rowptr[i] + g_bsum[i >> 10];
        g_rowptr[i] = excl;
        g_cnt[i]    = excl;
    }
    if (i == 0) g_rowptr[N_NODES_] = NNZ_;
}

__global__ void k_scatter(const int* __restrict__ rows, const int* __restrict__ cols,
                          const float* __restrict__ vals) {
    int i = blockIdx.x * blockDim.x + threadIdx.x;
    if (i < NNZ_) {
        int p = atomicAdd(&g_cnt[rows[i]], 1);
        g_cols[p] = cols[i];
        g_vals[p] = vals[i];
    }
}

// ---------------- E init + blend scatter ----------------
__global__ void k_init_E(const float4* __restrict__ user_tab, const float4* __restrict__ item_tab) {
    int i = blockIdx.x * blockDim.x + threadIdx.x;
    const int tot_u = N_USER * EMBV;
    const int tot   = N_NODES_ * EMBV;
    if (i < tot_u)      ((float4*)g_E0)[i] = user_tab[i];
    else if (i < tot)   ((float4*)g_E0)[i] = item_tab[i - tot_u];
}

__global__ void k_winner(const int* __restrict__ u_id) {
    int i = blockIdx.x * blockDim.x + threadIdx.x;
    if (i < BATCH_) atomicMax(&g_winner[u_id[i]], i);
}

__global__ void k_blend(const int* __restrict__ u_id, const int* __restrict__ age,
                        const int* __restrict__ sex, const int* __restrict__ month,
                        const int* __restrict__ day, const int* __restrict__ dow,
                        const float* __restrict__ user_tab,
                        const float* __restrict__ age_tab, const float* __restrict__ sex_tab,
                        const float* __restrict__ month_tab, const float* __restrict__ day_tab,
                        const float* __restrict__ dow_tab) {
    int i = blockIdx.x * blockDim.x + threadIdx.x;
    if (i >= BATCH_) return;
    int u = u_id[i];
    if (g_winner[u] != i) return;   // last occurrence wins
    float*       dst = g_E0 + (size_t)u * EMB;
    const float* src = user_tab + (size_t)u * EMB;
    const float* t0 = age_tab   + age[i]   * FEAT;
    const float* t1 = sex_tab   + sex[i]   * FEAT;
    const float* t2 = month_tab + month[i] * FEAT;
    const float* t3 = day_tab   + day[i]   * FEAT;
    const float* t4 = dow_tab   + dow[i]   * FEAT;
    #pragma unroll
    for (int j = 0; j < FEAT; j++) {
        dst[0*FEAT+j] = 0.5f * (src[0*FEAT+j] + t0[j]);
        dst[1*FEAT+j] = 0.5f * (src[1*FEAT+j] + t1[j]);
        dst[2*FEAT+j] = 0.5f * (src[2*FEAT+j] + t2[j]);
        dst[3*FEAT+j] = 0.5f * (src[3*FEAT+j] + t3[j]);
        dst[4*FEAT+j] = 0.5f * (src[4*FEAT+j] + t4[j]);
    }
}

// ---------------- fused layer: SpMM + dual GEMM + bias + leaky ----------------
// Per 64-row block:
//   LE = Lap @ Ein   (gathered rows, staged straight into shared X tile)
//   X  = [LE+Ein | LE*Ein]  (64 x 160 in shared)
//   Eout = leaky( X @ [W1;W2] + 2*b1 + b2 )
#define GBM 64
#define GT  160
#define XS  164   // padded row stride (floats)
#define WROWQ 20  // ulonglong2 per W row (80 floats = 320 B = 20 x 16 B)

__global__ __launch_bounds__(GT) void k_layer(const float* __restrict__ W1l,
                                              const float* __restrict__ b1l,
                                              const float* __restrict__ W2l,
                                              const float* __restrict__ b2l,
                                              const float* __restrict__ Ein,
                                              float* __restrict__ Eout) {
    __shared__ float Xs[GBM * XS];   // 41.98 KB
    __shared__ float Bs[EMB];

    int tid  = threadIdx.x;
    int row0 = blockIdx.x * GBM;

    if (tid < EMB) Bs[tid] = 2.0f * b1l[tid] + b2l[tid];

    // ---- SpMM phase: 8 groups of 20 threads, one row per group ----
    {
        int grp = tid / EMBV;          // 0..7
        int ln  = tid % EMBV;          // float4 chunk 0..19
        const float4* E4 = (const float4*)Ein;
        for (int rr = grp; rr < GBM; rr += 8) {
            int gr = row0 + rr;
            float4 a = make_float4(0.f, 0.f, 0.f, 0.f);
            float4 e = a;
            if (gr < N_NODES_) {
                int s = g_rowptr[gr], en = g_rowptr[gr + 1];
                for (int i = s; i < en; i++) {
                    float v = g_vals[i];
                    int   c = g_cols[i];
                    float4 x = __ldg(&E4[(size_t)c * EMBV + ln]);
                    a.x = fmaf(v, x.x, a.x);
                    a.y = fmaf(v, x.y, a.y);
                    a.z = fmaf(v, x.z, a.z);
                    a.w = fmaf(v, x.w, a.w);
                }
                e = E4[(size_t)gr * EMBV + ln];
            }
            float4* xr = (float4*)(Xs + rr * XS);
            xr[ln]        = make_float4(a.x + e.x, a.y + e.y, a.z + e.z, a.w + e.w);
            xr[EMBV + ln] = make_float4(a.x * e.x, a.y * e.y, a.z * e.z, a.w * e.w);
        }
    }
    __syncthreads();

    // ---- GEMM phase: f32x2 packed FMA ----
    // tx = col-group (8 cols), ty = row-group (4 rows)
    int tx = tid % 10;
    int ty = tid / 10;

    ull acc[4][4];
    #pragma unroll
    for (int r = 0; r < 4; r++)
        #pragma unroll
        for (int j = 0; j < 4; j++) acc[r][j] = 0ull;

    const ulonglong2* Wq1 = (const ulonglong2*)W1l;  // row k: 20 x ulonglong2
    const ulonglong2* Wq2 = (const ulonglong2*)W2l;

    #pragma unroll
    for (int half = 0; half < 2; half++) {
        const ulonglong2* Wq = half ? Wq2 : Wq1;
        const float* xb = Xs + half * EMB;
        for (int k = 0; k < EMB; k += 4) {
            ulonglong2 w0a = __ldg(&Wq[(k + 0) * WROWQ + tx * 2]);
            ulonglong2 w0b = __ldg(&Wq[(k + 0) * WROWQ + tx * 2 + 1]);
            ulonglong2 w1a = __ldg(&Wq[(k + 1) * WROWQ + tx * 2]);
            ulonglong2 w1b = __ldg(&Wq[(k + 1) * WROWQ + tx * 2 + 1]);
            ulonglong2 w2a = __ldg(&Wq[(k + 2) * WROWQ + tx * 2]);
            ulonglong2 w2b = __ldg(&Wq[(k + 2) * WROWQ + tx * 2 + 1]);
            ulonglong2 w3a = __ldg(&Wq[(k + 3) * WROWQ + tx * 2]);
            ulonglong2 w3b = __ldg(&Wq[(k + 3) * WROWQ + tx * 2 + 1]);
            #pragma unroll
            for (int r = 0; r < 4; r++) {
                float4 xv = *(const float4*)(xb + (ty * 4 + r) * XS + k);
                ull bx = bcast2(xv.x);
                acc[r][0] = fma2(bx, w0a.x, acc[r][0]);
                acc[r][1] = fma2(bx, w0a.y, acc[r][1]);
                acc[r][2] = fma2(bx, w0b.x, acc[r][2]);
                acc[r][3] = fma2(bx, w0b.y, acc[r][3]);
                ull by = bcast2(xv.y);
                acc[r][0] = fma2(by, w1a.x, acc[r][0]);
                acc[r][1] = fma2(by, w1a.y, acc[r][1]);
                acc[r][2] = fma2(by, w1b.x, acc[r][2]);
                acc[r][3] = fma2(by, w1b.y, acc[r][3]);
                ull bz = bcast2(xv.z);
                acc[r][0] = fma2(bz, w2a.x, acc[r][0]);
                acc[r][1] = fma2(bz, w2a.y, acc[r][1]);
                acc[r][2] = fma2(bz, w2b.x, acc[r][2]);
                acc[r][3] = fma2(bz, w2b.y, acc[r][3]);
                ull bw = bcast2(xv.w);
                acc[r][0] = fma2(bw, w3a.x, acc[r][0]);
                acc[r][1] = fma2(bw, w3a.y, acc[r][1]);
                acc[r][2] = fma2(bw, w3b.x, acc[r][2]);
                acc[r][3] = fma2(bw, w3b.y, acc[r][3]);
            }
        }
    }

    // ---- epilogue: bias + leaky relu, write to Eout ----
    float bsc[8];
    #pragma unroll
    for (int j = 0; j < 8; j++) bsc[j] = Bs[tx * 8 + j];

    #pragma unroll
    for (int r = 0; r < 4; r++) {
        int gr = row0 + ty * 4 + r;
        if (gr >= N_NODES_) continue;
        float2 a0 = unpk(acc[r][0]);
        float2 a1 = unpk(acc[r][1]);
        float2 a2 = unpk(acc[r][2]);
        float2 a3 = unpk(acc[r][3]);
        float v[8] = { a0.x + bsc[0], a0.y + bsc[1], a1.x + bsc[2], a1.y + bsc[3],
                       a2.x + bsc[4], a2.y + bsc[5], a3.x + bsc[6], a3.y + bsc[7] };
        #pragma unroll
        for (int j = 0; j < 8; j++) v[j] = (v[j] > 0.f) ? v[j] : 0.2f * v[j];
        float4* o = (float4*)(Eout + (size_t)gr * EMB + tx * 8);
        o[0] = make_float4(v[0], v[1], v[2], v[3]);
        o[1] = make_float4(v[4], v[5], v[6], v[7]);
    }
}

// ---------------- gather + row-normalize selected rows into output ----------------
__global__ void k_gather(const int* __restrict__ u_id, const int* __restrict__ pos,
                         const int* __restrict__ neg, const float* __restrict__ E,
                         float* __restrict__ out, int layer) {
    int gw   = (blockIdx.x * blockDim.x + threadIdx.x) >> 5;
    int lane = threadIdx.x & 31;
    if (gw >= 3 * BATCH_) return;
    int node;
    if (gw < BATCH_)          node = u_id[gw];
    else if (gw < 2 * BATCH_) node = N_USER + pos[gw - BATCH_];
    else                      node = N_USER + neg[gw - 2 * BATCH_];

    const float4* E4 = (const float4*)E;
    float4 v = make_float4(0.f, 0.f, 0.f, 0.f);
    if (lane < EMBV) v = E4[(size_t)node * EMBV + lane];
    float ss = v.x * v.x + v.y * v.y + v.z * v.z + v.w * v.w;
    #pragma unroll
    for (int o = 16; o; o >>= 1) ss += __shfl_xor_sync(0xffffffffu, ss, o);
    float scale = 1.0f;
    if (layer > 0) scale = 1.0f / fmaxf(sqrtf(ss), 1e-12f);
    if (lane < EMBV) {
        float4 r = make_float4(v.x * scale, v.y * scale, v.z * scale, v.w * scale);
        ((float4*)(out + (size_t)gw * (4 * EMB) + layer * EMB))[lane] = r;
    }
}

// ---------------- launch ----------------
extern "C" void kernel_launch(void* const* d_in, const int* in_sizes, int n_in,
                              void* d_out, int out_size) {
    const int*   u_id      = (const int*)d_in[0];
    const int*   age       = (const int*)d_in[1];
    const int*   sex       = (const int*)d_in[2];
    const int*   month     = (const int*)d_in[3];
    const int*   day       = (const int*)d_in[4];
    const int*   dow       = (const int*)d_in[5];
    const int*   pos       = (const int*)d_in[6];
    const int*   neg       = (const int*)d_in[7];
    const int*   lrows     = (const int*)d_in[8];
    const int*   lcols     = (const int*)d_in[9];
    const float* lvals     = (const float*)d_in[10];
    const float* user_tab  = (const float*)d_in[11];
    const float* item_tab  = (const float*)d_in[12];
    const float* age_tab   = (const float*)d_in[13];
    const float* sex_tab   = (const float*)d_in[14];
    const float* month_tab = (const float*)d_in[15];
    const float* day_tab   = (const float*)d_in[16];
    const float* dow_tab   = (const float*)d_in[17];
    const float* W1        = (const float*)d_in[18];
    const float* b1        = (const float*)d_in[19];
    const float* W2        = (const float*)d_in[20];
    const float* b2        = (const float*)d_in[21];
    float* out = (float*)d_out;

    // Resolve device addresses of __device__ scratch FIRST (host shadow symbol
    // is NOT a device pointer — passing it as a kernel arg was the R2-R4 bug).
    float* bufs[2] = { nullptr, nullptr };
    cudaGetSymbolAddress((void**)&bufs[0], g_E0);
    cudaGetSymbolAddress((void**)&bufs[1], g_E1);

    // CSR build (reused by all 3 layers)
    k_init<<<(N_NODES_ + 255) / 256, 256>>>();
    k_hist<<<(NNZ_ + 255) / 256, 256>>>(lrows);
    int nb = (N_NODES_ + 1023) / 1024;
    k_scan1<<<nb, 1024>>>();
    k_scan2<<<1, 1024>>>(nb);
    k_scan3<<<(N_NODES_ + 255) / 256, 256>>>();
    k_scatter<<<(NNZ_ + 255) / 256, 256>>>(lrows, lcols, lvals);

    // E0 = concat(user_tab with blended rows, item_tab)
    k_init_E<<<(N_NODES_ * EMBV + 255) / 256, 256>>>((const float4*)user_tab,
                                                     (const float4*)item_tab);
    k_winner<<<(BATCH_ + 255) / 256, 256>>>(u_id);
    k_blend<<<(BATCH_ + 255) / 256, 256>>>(u_id, age, sex, month, day, dow, user_tab,
                                           age_tab, sex_tab, month_tab, day_tab, dow_tab);

    // layer-0 slice (unnormalized E0) — pass the REAL device address
    k_gather<<<(3 * BATCH_ * 32 + 255) / 256, 256>>>(u_id, pos, neg, bufs[0], out, 0);

    int gb = (N_NODES_ + GBM - 1) / GBM;
    for (int l = 0; l < NLAYER; l++) {
        const float* Ein = bufs[l & 1];
        float*       Eo  = bufs[(l + 1) & 1];
        k_layer<<<gb, GT>>>(W1 + (size_t)l * EMB * EMB, b1 + l * EMB,
                            W2 + (size_t)l * EMB * EMB, b2 + l * EMB, Ein, Eo);
        k_gather<<<(3 * BATCH_ * 32 + 255) / 256, 256>>>(u_id, pos, neg, Eo, out, l + 1);
    }
}

// round 9
// speedup vs baseline: 1.0043x; 1.0043x over previous
#include <cuda_runtime.h>

#define N_USER   200000
#define N_ITEM   100000
#define N_NODES_ 300000
#define EMB      80
#define EMBV     20          // float4 chunks per row
#define FEAT     16
#define NNZ_     1000000
#define BATCH_   4096
#define NLAYER   3

typedef unsigned long long ull;

// ---------------- device scratch ----------------
static __device__ float g_E [(size_t)N_NODES_ * EMB];   // 96 MB
static __device__ float g_LE[(size_t)N_NODES_ * EMB];   // 96 MB
static __device__ int   g_rowptr[N_NODES_ + 1];
static __device__ int   g_cnt[N_NODES_];
static __device__ int   g_bsum[1024];
static __device__ int   g_winner[N_USER];
static __device__ int   g_cols[NNZ_];
static __device__ float g_vals[NNZ_];

// ---------------- f32x2 helpers ----------------
__device__ __forceinline__ ull fma2(ull a, ull b, ull c) {
    ull d;
    asm("fma.rn.f32x2 %0, %1, %2, %3;" : "=l"(d) : "l"(a), "l"(b), "l"(c));
    return d;
}
__device__ __forceinline__ ull bcast2(float x) {
    ull d;
    asm("mov.b64 %0, {%1, %1};" : "=l"(d) : "f"(x));
    return d;
}
__device__ __forceinline__ float2 unpk(ull v) {
    float2 r;
    asm("mov.b64 {%0, %1}, %2;" : "=f"(r.x), "=f"(r.y) : "l"(v));
    return r;
}

// ---------------- CSR build ----------------
__global__ void k_init() {
    int i = blockIdx.x * blockDim.x + threadIdx.x;
    if (i < N_NODES_) g_cnt[i] = 0;
    if (i < N_USER)   g_winner[i] = -1;
}

__global__ void k_hist(const int* __restrict__ rows) {
    int i = blockIdx.x * blockDim.x + threadIdx.x;
    if (i < NNZ_) atomicAdd(&g_cnt[rows[i]], 1);
}

__global__ void k_scan1() {
    __shared__ int s[1024];
    int tid = threadIdx.x;
    int i = blockIdx.x * 1024 + tid;
    int v = (i < N_NODES_) ? g_cnt[i] : 0;
    s[tid] = v; __syncthreads();
    for (int off = 1; off < 1024; off <<= 1) {
        int t = (tid >= off) ? s[tid - off] : 0;
        __syncthreads();
        s[tid] += t;
        __syncthreads();
    }
    if (i < N_NODES_) g_rowptr[i] = s[tid] - v;
    if (tid == 1023) g_bsum[blockIdx.x] = s[1023];
}

__global__ void k_scan2(int nb) {
    __shared__ int s[1024];
    int tid = threadIdx.x;
    int v = (tid < nb) ? g_bsum[tid] : 0;
    s[tid] = v; __syncthreads();
    for (int off = 1; off < 1024; off <<= 1) {
        int t = (tid >= off) ? s[tid - off] : 0;
        __syncthreads();
        s[tid] += t;
        __syncthreads();
    }
    if (tid < nb) g_bsum[tid] = s[tid] - v;
}

__global__ void k_scan3() {
    int i = blockIdx.x * blockDim.x + threadIdx.x;
    if (i < N_NODES_) {
        int excl = g_rowptr[i] + g_bsum[i >> 10];
        g_rowptr[i] = excl;
        g_cnt[i]    = excl;
    }
    if (i == 0) g_rowptr[N_NODES_] = NNZ_;
}

__global__ void k_scatter(const int* __restrict__ rows, const int* __restrict__ cols,
                          const float* __restrict__ vals) {
    int i = blockIdx.x * blockDim.x + threadIdx.x;
    if (i < NNZ_) {
        int p = atomicAdd(&g_cnt[rows[i]], 1);
        g_cols[p] = cols[i];
        g_vals[p] = vals[i];
    }
}

// ---------------- E init + blend scatter ----------------
__global__ void k_init_E(const float4* __restrict__ user_tab, const float4* __restrict__ item_tab) {
    int i = blockIdx.x * blockDim.x + threadIdx.x;
    const int tot_u = N_USER * EMBV;
    const int tot   = N_NODES_ * EMBV;
    if (i < tot_u)      ((float4*)g_E)[i] = user_tab[i];
    else if (i < tot)   ((float4*)g_E)[i] = item_tab[i - tot_u];
}

__global__ void k_winner(const int* __restrict__ u_id) {
    int i = blockIdx.x * blockDim.x + threadIdx.x;
    if (i < BATCH_) atomicMax(&g_winner[u_id[i]], i);
}

__global__ void k_blend(const int* __restrict__ u_id, const int* __restrict__ age,
                        const int* __restrict__ sex, const int* __restrict__ month,
                        const int* __restrict__ day, const int* __restrict__ dow,
                        const float* __restrict__ user_tab,
                        const float* __restrict__ age_tab, const float* __restrict__ sex_tab,
                        const float* __restrict__ month_tab, const float* __restrict__ day_tab,
                        const float* __restrict__ dow_tab) {
    int i = blockIdx.x * blockDim.x + threadIdx.x;
    if (i >= BATCH_) return;
    int u = u_id[i];
    if (g_winner[u] != i) return;   // last occurrence wins
    float*       dst = g_E + (size_t)u * EMB;
    const float* src = user_tab + (size_t)u * EMB;
    const float* t0 = age_tab   + age[i]   * FEAT;
    const float* t1 = sex_tab   + sex[i]   * FEAT;
    const float* t2 = month_tab + month[i] * FEAT;
    const float* t3 = day_tab   + day[i]   * FEAT;
    const float* t4 = dow_tab   + dow[i]   * FEAT;
    #pragma unroll
    for (int j = 0; j < FEAT; j++) {
        dst[0*FEAT+j] = 0.5f * (src[0*FEAT+j] + t0[j]);
        dst[1*FEAT+j] = 0.5f * (src[1*FEAT+j] + t1[j]);
        dst[2*FEAT+j] = 0.5f * (src[2*FEAT+j] + t2[j]);
        dst[3*FEAT+j] = 0.5f * (src[3*FEAT+j] + t3[j]);
        dst[4*FEAT+j] = 0.5f * (src[4*FEAT+j] + t4[j]);
    }
}

// ---------------- SpMM: L_E = Laplacian @ E (warp per row) ----------------
__global__ void k_spmm() {
    int gw   = (blockIdx.x * blockDim.x + threadIdx.x) >> 5;
    int lane = threadIdx.x & 31;
    int nw   = (gridDim.x * blockDim.x) >> 5;
    const float4* E4 = (const float4*)g_E;
    float4*       L4 = (float4*)g_LE;
    for (int row = gw; row < N_NODES_; row += nw) {
        int s = g_rowptr[row], e = g_rowptr[row + 1];
        if (lane < EMBV) {
            float4 acc = make_float4(0.f, 0.f, 0.f, 0.f);
            for (int i = s; i < e; i++) {
                float v = g_vals[i];
                int   c = g_cols[i];
                float4 x = __ldg(&E4[(size_t)c * EMBV + lane]);
                acc.x = fmaf(v, x.x, acc.x);
                acc.y = fmaf(v, x.y, acc.y);
                acc.z = fmaf(v, x.z, acc.z);
                acc.w = fmaf(v, x.w, acc.w);
            }
            L4[(size_t)row * EMBV + lane] = acc;
        }
    }
}

// ---------------- GEMM + bias + leaky, in-place E update (f32x2 core) ----------------
// msg = (L_E+E)@W1 + 2*b1 + (L_E*E)@W2 + b2 ; E = leaky_relu(msg)
#define GBM 64
#define GT  160
#define XS  164   // padded row stride (floats)
#define WROWQ 20  // ulonglong2 per W row (80 floats = 320 B)

__global__ __launch_bounds__(GT) void k_gemm(const float* __restrict__ W1l,
                                             const float* __restrict__ b1l,
                                             const float* __restrict__ W2l,
                                             const float* __restrict__ b2l) {
    __shared__ float Xs[GBM * XS];   // 41.98 KB
    __shared__ float Bs[EMB];

    int tid  = threadIdx.x;
    int row0 = blockIdx.x * GBM;

    if (tid < EMB) Bs[tid] = 2.0f * b1l[tid] + b2l[tid];

    // ---- stage X = [LE+E | LE*E] from global (round-1 staging) ----
    const float4* E4 = (const float4*)g_E;
    const float4* L4 = (const float4*)g_LE;
    for (int j = tid; j < GBM * EMBV; j += GT) {
        int r = j / EMBV, c = j % EMBV;
        int gr = row0 + r;
        float4 le = make_float4(0.f, 0.f, 0.f, 0.f), e = le;
        if (gr < N_NODES_) {
            le = L4[(size_t)gr * EMBV + c];
            e  = E4[(size_t)gr * EMBV + c];
        }
        float4* xr = (float4*)(Xs + r * XS);
        xr[c]        = make_float4(le.x + e.x, le.y + e.y, le.z + e.z, le.w + e.w);
        xr[EMBV + c] = make_float4(le.x * e.x, le.y * e.y, le.z * e.z, le.w * e.w);
    }
    __syncthreads();

    // ---- f32x2 GEMM: tx = col-group (8 cols), ty = row-group (4 rows) ----
    int tx = tid % 10;
    int ty = tid / 10;

    ull acc[4][4];
    #pragma unroll
    for (int r = 0; r < 4; r++)
        #pragma unroll
        for (int j = 0; j < 4; j++) acc[r][j] = 0ull;

    const ulonglong2* Wq1 = (const ulonglong2*)W1l;
    const ulonglong2* Wq2 = (const ulonglong2*)W2l;

    #pragma unroll
    for (int half = 0; half < 2; half++) {
        const ulonglong2* Wq = half ? Wq2 : Wq1;
        const float* xb = Xs + half * EMB;
        for (int k = 0; k < EMB; k += 4) {
            ulonglong2 w0a = __ldg(&Wq[(k + 0) * WROWQ + tx * 2]);
            ulonglong2 w0b = __ldg(&Wq[(k + 0) * WROWQ + tx * 2 + 1]);
            ulonglong2 w1a = __ldg(&Wq[(k + 1) * WROWQ + tx * 2]);
            ulonglong2 w1b = __ldg(&Wq[(k + 1) * WROWQ + tx * 2 + 1]);
            ulonglong2 w2a = __ldg(&Wq[(k + 2) * WROWQ + tx * 2]);
            ulonglong2 w2b = __ldg(&Wq[(k + 2) * WROWQ + tx * 2 + 1]);
            ulonglong2 w3a = __ldg(&Wq[(k + 3) * WROWQ + tx * 2]);
            ulonglong2 w3b = __ldg(&Wq[(k + 3) * WROWQ + tx * 2 + 1]);
            #pragma unroll
            for (int r = 0; r < 4; r++) {
                float4 xv = *(const float4*)(xb + (ty * 4 + r) * XS + k);
                ull bx = bcast2(xv.x);
                acc[r][0] = fma2(bx, w0a.x, acc[r][0]);
                acc[r][1] = fma2(bx, w0a.y, acc[r][1]);
                acc[r][2] = fma2(bx, w0b.x, acc[r][2]);
                acc[r][3] = fma2(bx, w0b.y, acc[r][3]);
                ull by = bcast2(xv.y);
                acc[r][0] = fma2(by, w1a.x, acc[r][0]);
                acc[r][1] = fma2(by, w1a.y, acc[r][1]);
                acc[r][2] = fma2(by, w1b.x, acc[r][2]);
                acc[r][3] = fma2(by, w1b.y, acc[r][3]);
                ull bz = bcast2(xv.z);
                acc[r][0] = fma2(bz, w2a.x, acc[r][0]);
                acc[r][1] = fma2(bz, w2a.y, acc[r][1]);
                acc[r][2] = fma2(bz, w2b.x, acc[r][2]);
                acc[r][3] = fma2(bz, w2b.y, acc[r][3]);
                ull bw = bcast2(xv.w);
                acc[r][0] = fma2(bw, w3a.x, acc[r][0]);
                acc[r][1] = fma2(bw, w3a.y, acc[r][1]);
                acc[r][2] = fma2(bw, w3b.x, acc[r][2]);
                acc[r][3] = fma2(bw, w3b.y, acc[r][3]);
            }
        }
    }

    // ---- epilogue: bias + leaky relu, in-place write to g_E ----
    float bsc[8];
    #pragma unroll
    for (int j = 0; j < 8; j++) bsc[j] = Bs[tx * 8 + j];

    #pragma unroll
    for (int r = 0; r < 4; r++) {
        int gr = row0 + ty * 4 + r;
        if (gr >= N_NODES_) continue;
        float2 a0 = unpk(acc[r][0]);
        float2 a1 = unpk(acc[r][1]);
        float2 a2 = unpk(acc[r][2]);
        float2 a3 = unpk(acc[r][3]);
        float v[8] = { a0.x + bsc[0], a0.y + bsc[1], a1.x + bsc[2], a1.y + bsc[3],
                       a2.x + bsc[4], a2.y + bsc[5], a3.x + bsc[6], a3.y + bsc[7] };
        #pragma unroll
        for (int j = 0; j < 8; j++) v[j] = (v[j] > 0.f) ? v[j] : 0.2f * v[j];
        float4* o = (float4*)(g_E + (size_t)gr * EMB + tx * 8);
        o[0] = make_float4(v[0], v[1], v[2], v[3]);
        o[1] = make_float4(v[4], v[5], v[6], v[7]);
    }
}

// ---------------- gather + row-normalize selected rows into output ----------------
__global__ void k_gather(const int* __restrict__ u_id, const int* __restrict__ pos,
                         const int* __restrict__ neg, float* __restrict__ out, int layer) {
    int gw   = (blockIdx.x * blockDim.x + threadIdx.x) >> 5;
    int lane = threadIdx.x & 31;
    if (gw >= 3 * BATCH_) return;
    int node;
    if (gw < BATCH_)          node = u_id[gw];
    else if (gw < 2 * BATCH_) node = N_USER + pos[gw - BATCH_];
    else                      node = N_USER + neg[gw - 2 * BATCH_];

    const float4* E4 = (const float4*)g_E;
    float4 v = make_float4(0.f, 0.f, 0.f, 0.f);
    if (lane < EMBV) v = E4[(size_t)node * EMBV + lane];
    float ss = v.x * v.x + v.y * v.y + v.z * v.z + v.w * v.w;
    #pragma unroll
    for (int o = 16; o; o >>= 1) ss += __shfl_xor_sync(0xffffffffu, ss, o);
    float scale = 1.0f;
    if (layer > 0) scale = 1.0f / fmaxf(sqrtf(ss), 1e-12f);
    if (lane < EMBV) {
        float4 r = make_float4(v.x * scale, v.y * scale, v.z * scale, v.w * scale);
        ((float4*)(out + (size_t)gw * (4 * EMB) + layer * EMB))[lane] = r;
    }
}

// ---------------- launch ----------------
extern "C" void kernel_launch(void* const* d_in, const int* in_sizes, int n_in,
                              void* d_out, int out_size) {
    const int*   u_id      = (const int*)d_in[0];
    const int*   age       = (const int*)d_in[1];
    const int*   sex       = (const int*)d_in[2];
    const int*   month     = (const int*)d_in[3];
    const int*   day       = (const int*)d_in[4];
    const int*   dow       = (const int*)d_in[5];
    const int*   pos       = (const int*)d_in[6];
    const int*   neg       = (const int*)d_in[7];
    const int*   lrows     = (const int*)d_in[8];
    const int*   lcols     = (const int*)d_in[9];
    const float* lvals     = (const float*)d_in[10];
    const float* user_tab  = (const float*)d_in[11];
    const float* item_tab  = (const float*)d_in[12];
    const float* age_tab   = (const float*)d_in[13];
    const float* sex_tab   = (const float*)d_in[14];
    const float* month_tab = (const float*)d_in[15];
    const float* day_tab   = (const float*)d_in[16];
    const float* dow_tab   = (const float*)d_in[17];
    const float* W1        = (const float*)d_in[18];
    const float* b1        = (const float*)d_in[19];
    const float* W2        = (const float*)d_in[20];
    const float* b2        = (const float*)d_in[21];
    float* out = (float*)d_out;

    // CSR build (reused by all 3 layers)
    k_init<<<(N_NODES_ + 255) / 256, 256>>>();
    k_hist<<<(NNZ_ + 255) / 256, 256>>>(lrows);
    int nb = (N_NODES_ + 1023) / 1024;
    k_scan1<<<nb, 1024>>>();
    k_scan2<<<1, 1024>>>(nb);
    k_scan3<<<(N_NODES_ + 255) / 256, 256>>>();
    k_scatter<<<(NNZ_ + 255) / 256, 256>>>(lrows, lcols, lvals);

    // E0 = concat(user_tab with blended rows, item_tab)
    k_init_E<<<(N_NODES_ * EMBV + 255) / 256, 256>>>((const float4*)user_tab,
                                                     (const float4*)item_tab);
    k_winner<<<(BATCH_ + 255) / 256, 256>>>(u_id);
    k_blend<<<(BATCH_ + 255) / 256, 256>>>(u_id, age, sex, month, day, dow, user_tab,
                                           age_tab, sex_tab, month_tab, day_tab, dow_tab);

    // layer-0 slice of the output (unnormalized E0)
    k_gather<<<(3 * BATCH_ * 32 + 255) / 256, 256>>>(u_id, pos, neg, out, 0);

    for (int l = 0; l < NLAYER; l++) {
        k_spmm<<<2048, 256>>>();
        k_gemm<<<(N_NODES_ + GBM - 1) / GBM, GT>>>(W1 + (size_t)l * EMB * EMB, b1 + l * EMB,
                                                   W2 + (size_t)l * EMB * EMB, b2 + l * EMB);
        k_gather<<<(3 * BATCH_ * 32 + 255) / 256, 256>>>(u_id, pos, neg, out, l + 1);
    }
}

// round 11
// speedup vs baseline: 1.8754x; 1.8673x over previous
#include <cuda_runtime.h>

#define N_USER   200000
#define N_ITEM   100000
#define N_NODES_ 300000
#define EMB      80
#define EMBV     20          // float4 chunks per row
#define FEAT     16
#define NNZ_     1000000
#define BATCH_   4096
#define NSEL     (3 * BATCH_)   // 12288 selected rows
#define NLAYER   3

// ---------------- device scratch ----------------
static __device__ float g_E [(size_t)N_NODES_ * EMB];   // 96 MB
static __device__ float g_LE[(size_t)N_NODES_ * EMB];   // 96 MB
static __device__ float g_LEsel[(size_t)NSEL * EMB];    // 3.9 MB (entry-indexed)
static __device__ float g_Esel [(size_t)NSEL * EMB];    // 3.9 MB (entry-indexed)
static __device__ int   g_nodes[NSEL];
static __device__ int   g_rowptr[N_NODES_ + 1];
static __device__ int   g_cnt[N_NODES_];
static __device__ int   g_bsum[1024];
static __device__ int   g_winner[N_USER];
static __device__ int   g_cols[NNZ_];
static __device__ float g_vals[NNZ_];

// ---------------- CSR build ----------------
__global__ void k_init() {
    int i = blockIdx.x * blockDim.x + threadIdx.x;
    if (i < N_NODES_) g_cnt[i] = 0;
    if (i < N_USER)   g_winner[i] = -1;
}

__global__ void k_hist(const int* __restrict__ rows) {
    int i = blockIdx.x * blockDim.x + threadIdx.x;
    if (i < NNZ_) atomicAdd(&g_cnt[rows[i]], 1);
}

__global__ void k_scan1() {
    __shared__ int s[1024];
    int tid = threadIdx.x;
    int i = blockIdx.x * 1024 + tid;
    int v = (i < N_NODES_) ? g_cnt[i] : 0;
    s[tid] = v; __syncthreads();
    for (int off = 1; off < 1024; off <<= 1) {
        int t = (tid >= off) ? s[tid - off] : 0;
        __syncthreads();
        s[tid] += t;
        __syncthreads();
    }
    if (i < N_NODES_) g_rowptr[i] = s[tid] - v;
    if (tid == 1023) g_bsum[blockIdx.x] = s[1023];
}

__global__ void k_scan2(int nb) {
    __shared__ int s[1024];
    int tid = threadIdx.x;
    int v = (tid < nb) ? g_bsum[tid] : 0;
    s[tid] = v; __syncthreads();
    for (int off = 1; off < 1024; off <<= 1) {
        int t = (tid >= off) ? s[tid - off] : 0;
        __syncthreads();
        s[tid] += t;
        __syncthreads();
    }
    if (tid < nb) g_bsum[tid] = s[tid] - v;
}

__global__ void k_scan3() {
    int i = blockIdx.x * blockDim.x + threadIdx.x;
    if (i < N_NODES_) {
        int excl = g_rowptr[i] + g_bsum[i >> 10];
        g_rowptr[i] = excl;
        g_cnt[i]    = excl;
    }
    if (i == 0) g_rowptr[N_NODES_] = NNZ_;
}

__global__ void k_scatter(const int* __restrict__ rows, const int* __restrict__ cols,
                          const float* __restrict__ vals) {
    int i = blockIdx.x * blockDim.x + threadIdx.x;
    if (i < NNZ_) {
        int p = atomicAdd(&g_cnt[rows[i]], 1);
        g_cols[p] = cols[i];
        g_vals[p] = vals[i];
    }
}

// ---------------- E init + blend scatter + node list ----------------
__global__ void k_init_E(const float4* __restrict__ user_tab, const float4* __restrict__ item_tab) {
    int i = blockIdx.x * blockDim.x + threadIdx.x;
    const int tot_u = N_USER * EMBV;
    const int tot   = N_NODES_ * EMBV;
    if (i < tot_u)      ((float4*)g_E)[i] = user_tab[i];
    else if (i < tot)   ((float4*)g_E)[i] = item_tab[i - tot_u];
}

__global__ void k_winner(const int* __restrict__ u_id) {
    int i = blockIdx.x * blockDim.x + threadIdx.x;
    if (i < BATCH_) atomicMax(&g_winner[u_id[i]], i);
}

__global__ void k_blend(const int* __restrict__ u_id, const int* __restrict__ age,
                        const int* __restrict__ sex, const int* __restrict__ month,
                        const int* __restrict__ day, const int* __restrict__ dow,
                        const float* __restrict__ user_tab,
                        const float* __restrict__ age_tab, const float* __restrict__ sex_tab,
                        const float* __restrict__ month_tab, const float* __restrict__ day_tab,
                        const float* __restrict__ dow_tab) {
    int i = blockIdx.x * blockDim.x + threadIdx.x;
    if (i >= BATCH_) return;
    int u = u_id[i];
    if (g_winner[u] != i) return;   // last occurrence wins
    float*       dst = g_E + (size_t)u * EMB;
    const float* src = user_tab + (size_t)u * EMB;
    const float* t0 = age_tab   + age[i]   * FEAT;
    const float* t1 = sex_tab   + sex[i]   * FEAT;
    const float* t2 = month_tab + month[i] * FEAT;
    const float* t3 = day_tab   + day[i]   * FEAT;
    const float* t4 = dow_tab   + dow[i]   * FEAT;
    #pragma unroll
    for (int j = 0; j < FEAT; j++) {
        dst[0*FEAT+j] = 0.5f * (src[0*FEAT+j] + t0[j]);
        dst[1*FEAT+j] = 0.5f * (src[1*FEAT+j] + t1[j]);
        dst[2*FEAT+j] = 0.5f * (src[2*FEAT+j] + t2[j]);
        dst[3*FEAT+j] = 0.5f * (src[3*FEAT+j] + t3[j]);
        dst[4*FEAT+j] = 0.5f * (src[4*FEAT+j] + t4[j]);
    }
}

__global__ void k_nodes(const int* __restrict__ u_id, const int* __restrict__ pos,
                        const int* __restrict__ neg) {
    int i = blockIdx.x * blockDim.x + threadIdx.x;
    if (i >= NSEL) return;
    int node;
    if (i < BATCH_)          node = u_id[i];
    else if (i < 2 * BATCH_) node = N_USER + pos[i - BATCH_];
    else                     node = N_USER + neg[i - 2 * BATCH_];
    g_nodes[i] = node;
}

// ---------------- SpMM: L_E = Laplacian @ E (warp per row) ----------------
__global__ void k_spmm() {
    int gw   = (blockIdx.x * blockDim.x + threadIdx.x) >> 5;
    int lane = threadIdx.x & 31;
    int nw   = (gridDim.x * blockDim.x) >> 5;
    const float4* E4 = (const float4*)g_E;
    float4*       L4 = (float4*)g_LE;
    for (int row = gw; row < N_NODES_; row += nw) {
        int s = g_rowptr[row], e = g_rowptr[row + 1];
        if (lane < EMBV) {
            float4 acc = make_float4(0.f, 0.f, 0.f, 0.f);
            for (int i = s; i < e; i++) {
                float v = g_vals[i];
                int   c = g_cols[i];
                float4 x = __ldg(&E4[(size_t)c * EMBV + lane]);
                acc.x = fmaf(v, x.x, acc.x);
                acc.y = fmaf(v, x.y, acc.y);
                acc.z = fmaf(v, x.z, acc.z);
                acc.w = fmaf(v, x.w, acc.w);
            }
            L4[(size_t)row * EMBV + lane] = acc;
        }
    }
}

// Selective SpMM: only the NSEL selected rows, entry-indexed output.
__global__ void k_spmm_sel() {
    int gw   = (blockIdx.x * blockDim.x + threadIdx.x) >> 5;
    int lane = threadIdx.x & 31;
    if (gw >= NSEL) return;
    int row = g_nodes[gw];
    const float4* E4 = (const float4*)g_E;
    float4*       L4 = (float4*)g_LEsel;
    int s = g_rowptr[row], e = g_rowptr[row + 1];
    if (lane < EMBV) {
        float4 acc = make_float4(0.f, 0.f, 0.f, 0.f);
        for (int i = s; i < e; i++) {
            float v = g_vals[i];
            int   c = g_cols[i];
            float4 x = __ldg(&E4[(size_t)c * EMBV + lane]);
            acc.x = fmaf(v, x.x, acc.x);
            acc.y = fmaf(v, x.y, acc.y);
            acc.z = fmaf(v, x.z, acc.z);
            acc.w = fmaf(v, x.w, acc.w);
        }
        L4[(size_t)gw * EMBV + lane] = acc;
    }
}

// ---------------- GEMM + bias + leaky (proven round-1 scalar core) ----------------
// msg = (L_E+E)@W1 + 2*b1 + (L_E*E)@W2 + b2 ; E = leaky_relu(msg)
#define GBM 64
#define GT  160
#define XS  164   // padded row stride (floats)

__device__ __forceinline__ void fma4(float4& a, float s, const float4 w) {
    a.x = fmaf(s, w.x, a.x);
    a.y = fmaf(s, w.y, a.y);
    a.z = fmaf(s, w.z, a.z);
    a.w = fmaf(s, w.w, a.w);
}

// Shared inner core: X tile already staged in Xs; computes acc and writes epilogue.
__device__ __forceinline__ void gemm_core_epilogue(
        const float* Xs, const float* Bs, int tid,
        const float* __restrict__ W1l, const float* __restrict__ W2l,
        float4* __restrict__ out4, int row0, int row_limit, bool entry_indexed) {
    int tx = tid % EMBV;        // col chunk (float4), 0..19
    int ty = tid / EMBV;        // row group, 0..7 (8 rows each)

    float4 acc[8];
    #pragma unroll
    for (int r = 0; r < 8; r++) acc[r] = make_float4(0.f, 0.f, 0.f, 0.f);

    const float4* W14 = (const float4*)W1l;   // [80][20] float4
    const float4* W24 = (const float4*)W2l;
    const float*  xb  = Xs + (ty * 8) * XS;

    for (int k = 0; k < EMB; k += 4) {
        float4 w0 = __ldg(&W14[(k + 0) * EMBV + tx]);
        float4 w1 = __ldg(&W14[(k + 1) * EMBV + tx]);
        float4 w2 = __ldg(&W14[(k + 2) * EMBV + tx]);
        float4 w3 = __ldg(&W14[(k + 3) * EMBV + tx]);
        #pragma unroll
        for (int r = 0; r < 8; r++) {
            float4 xv = *(const float4*)(xb + r * XS + k);
            fma4(acc[r], xv.x, w0);
            fma4(acc[r], xv.y, w1);
            fma4(acc[r], xv.z, w2);
            fma4(acc[r], xv.w, w3);
        }
    }
    for (int k = 0; k < EMB; k += 4) {
        float4 w0 = __ldg(&W24[(k + 0) * EMBV + tx]);
        float4 w1 = __ldg(&W24[(k + 1) * EMBV + tx]);
        float4 w2 = __ldg(&W24[(k + 2) * EMBV + tx]);
        float4 w3 = __ldg(&W24[(k + 3) * EMBV + tx]);
        #pragma unroll
        for (int r = 0; r < 8; r++) {
            float4 xv = *(const float4*)(xb + r * XS + EMB + k);
            fma4(acc[r], xv.x, w0);
            fma4(acc[r], xv.y, w1);
            fma4(acc[r], xv.z, w2);
            fma4(acc[r], xv.w, w3);
        }
    }

    float4 b = ((const float4*)Bs)[tx];
    #pragma unroll
    for (int r = 0; r < 8; r++) {
        int gr = row0 + ty * 8 + r;
        if (gr < row_limit) {
            float4 v;
            v.x = acc[r].x + b.x;
            v.y = acc[r].y + b.y;
            v.z = acc[r].z + b.z;
            v.w = acc[r].w + b.w;
            v.x = (v.x > 0.f) ? v.x : 0.2f * v.x;
            v.y = (v.y > 0.f) ? v.y : 0.2f * v.y;
            v.z = (v.z > 0.f) ? v.z : 0.2f * v.z;
            v.w = (v.w > 0.f) ? v.w : 0.2f * v.w;
            out4[(size_t)gr * EMBV + tx] = v;
        }
    }
    (void)entry_indexed;
}

__global__ __launch_bounds__(GT) void k_gemm(const float* __restrict__ W1l,
                                             const float* __restrict__ b1l,
                                             const float* __restrict__ W2l,
                                             const float* __restrict__ b2l) {
    __shared__ float Xs[GBM * XS];   // 41.98 KB
    __shared__ float Bs[EMB];

    int tid  = threadIdx.x;
    int row0 = blockIdx.x * GBM;

    if (tid < EMB) Bs[tid] = 2.0f * b1l[tid] + b2l[tid];

    const float4* E4 = (const float4*)g_E;
    const float4* L4 = (const float4*)g_LE;
    for (int j = tid; j < GBM * EMBV; j += GT) {
        int r = j / EMBV, c = j % EMBV;
        int gr = row0 + r;
        float4 le = make_float4(0.f, 0.f, 0.f, 0.f), e = le;
        if (gr < N_NODES_) {
            le = L4[(size_t)gr * EMBV + c];
            e  = E4[(size_t)gr * EMBV + c];
        }
        float4* xr = (float4*)(Xs + r * XS);
        xr[c]        = make_float4(le.x + e.x, le.y + e.y, le.z + e.z, le.w + e.w);
        xr[EMBV + c] = make_float4(le.x * e.x, le.y * e.y, le.z * e.z, le.w * e.w);
    }
    __syncthreads();

    gemm_core_epilogue(Xs, Bs, tid, W1l, W2l, (float4*)g_E, row0, N_NODES_, false);
}

// Selective GEMM: 64 entries/block over the node list; entry-indexed output.
__global__ __launch_bounds__(GT) void k_gemm_sel(const float* __restrict__ W1l,
                                                 const float* __restrict__ b1l,
                                                 const float* __restrict__ W2l,
                                                 const float* __restrict__ b2l) {
    __shared__ float Xs[GBM * XS];
    __shared__ float Bs[EMB];

    int tid  = threadIdx.x;
    int row0 = blockIdx.x * GBM;   // entry index base (NSEL = 192*64 exact)

    if (tid < EMB) Bs[tid] = 2.0f * b1l[tid] + b2l[tid];

    const float4* E4 = (const float4*)g_E;
    const float4* L4 = (const float4*)g_LEsel;
    for (int j = tid; j < GBM * EMBV; j += GT) {
        int r = j / EMBV, c = j % EMBV;
        int entry = row0 + r;
        int node  = g_nodes[entry];
        float4 le = L4[(size_t)entry * EMBV + c];   // entry-indexed LE
        float4 e  = E4[(size_t)node  * EMBV + c];   // node-indexed E (read-only this layer)
        float4* xr = (float4*)(Xs + r * XS);
        xr[c]        = make_float4(le.x + e.x, le.y + e.y, le.z + e.z, le.w + e.w);
        xr[EMBV + c] = make_float4(le.x * e.x, le.y * e.y, le.z * e.z, le.w * e.w);
    }
    __syncthreads();

    gemm_core_epilogue(Xs, Bs, tid, W1l, W2l, (float4*)g_Esel, row0, NSEL, true);
}

// ---------------- gather + row-normalize selected rows into output ----------------
__global__ void k_gather(const int* __restrict__ u_id, const int* __restrict__ pos,
                         const int* __restrict__ neg, float* __restrict__ out, int layer) {
    int gw   = (blockIdx.x * blockDim.x + threadIdx.x) >> 5;
    int lane = threadIdx.x & 31;
    if (gw >= NSEL) return;
    int node;
    if (gw < BATCH_)          node = u_id[gw];
    else if (gw < 2 * BATCH_) node = N_USER + pos[gw - BATCH_];
    else                      node = N_USER + neg[gw - 2 * BATCH_];

    const float4* E4 = (const float4*)g_E;
    float4 v = make_float4(0.f, 0.f, 0.f, 0.f);
    if (lane < EMBV) v = E4[(size_t)node * EMBV + lane];
    float ss = v.x * v.x + v.y * v.y + v.z * v.z + v.w * v.w;
    #pragma unroll
    for (int o = 16; o; o >>= 1) ss += __shfl_xor_sync(0xffffffffu, ss, o);
    float scale = 1.0f;
    if (layer > 0) scale = 1.0f / fmaxf(sqrtf(ss), 1e-12f);
    if (lane < EMBV) {
        float4 r = make_float4(v.x * scale, v.y * scale, v.z * scale, v.w * scale);
        ((float4*)(out + (size_t)gw * (4 * EMB) + layer * EMB))[lane] = r;
    }
}

// Final layer gather: reads the entry-indexed selective buffer (always normalized).
__global__ void k_gather_sel(float* __restrict__ out, int layer) {
    int gw   = (blockIdx.x * blockDim.x + threadIdx.x) >> 5;
    int lane = threadIdx.x & 31;
    if (gw >= NSEL) return;
    const float4* E4 = (const float4*)g_Esel;
    float4 v = make_float4(0.f, 0.f, 0.f, 0.f);
    if (lane < EMBV) v = E4[(size_t)gw * EMBV + lane];
    float ss = v.x * v.x + v.y * v.y + v.z * v.z + v.w * v.w;
    #pragma unroll
    for (int o = 16; o; o >>= 1) ss += __shfl_xor_sync(0xffffffffu, ss, o);
    float scale = 1.0f / fmaxf(sqrtf(ss), 1e-12f);
    if (lane < EMBV) {
        float4 r = make_float4(v.x * scale, v.y * scale, v.z * scale, v.w * scale);
        ((float4*)(out + (size_t)gw * (4 * EMB) + layer * EMB))[lane] = r;
    }
}

// ---------------- launch ----------------
extern "C" void kernel_launch(void* const* d_in, const int* in_sizes, int n_in,
                              void* d_out, int out_size) {
    const int*   u_id      = (const int*)d_in[0];
    const int*   age       = (const int*)d_in[1];
    const int*   sex       = (const int*)d_in[2];
    const int*   month     = (const int*)d_in[3];
    const int*   day       = (const int*)d_in[4];
    const int*   dow       = (const int*)d_in[5];
    const int*   pos       = (const int*)d_in[6];
    const int*   neg       = (const int*)d_in[7];
    const int*   lrows     = (const int*)d_in[8];
    const int*   lcols     = (const int*)d_in[9];
    const float* lvals     = (const float*)d_in[10];
    const float* user_tab  = (const float*)d_in[11];
    const float* item_tab  = (const float*)d_in[12];
    const float* age_tab   = (const float*)d_in[13];
    const float* sex_tab   = (const float*)d_in[14];
    const float* month_tab = (const float*)d_in[15];
    const float* day_tab   = (const float*)d_in[16];
    const float* dow_tab   = (const float*)d_in[17];
    const float* W1        = (const float*)d_in[18];
    const float* b1        = (const float*)d_in[19];
    const float* W2        = (const float*)d_in[20];
    const float* b2        = (const float*)d_in[21];
    float* out = (float*)d_out;

    // CSR build (reused by all 3 layers)
    k_init<<<(N_NODES_ + 255) / 256, 256>>>();
    k_hist<<<(NNZ_ + 255) / 256, 256>>>(lrows);
    int nb = (N_NODES_ + 1023) / 1024;
    k_scan1<<<nb, 1024>>>();
    k_scan2<<<1, 1024>>>(nb);
    k_scan3<<<(N_NODES_ + 255) / 256, 256>>>();
    k_scatter<<<(NNZ_ + 255) / 256, 256>>>(lrows, lcols, lvals);

    // E0 = concat(user_tab with blended rows, item_tab); node list
    k_init_E<<<(N_NODES_ * EMBV + 255) / 256, 256>>>((const float4*)user_tab,
                                                     (const float4*)item_tab);
    k_winner<<<(BATCH_ + 255) / 256, 256>>>(u_id);
    k_blend<<<(BATCH_ + 255) / 256, 256>>>(u_id, age, sex, month, day, dow, user_tab,
                                           age_tab, sex_tab, month_tab, day_tab, dow_tab);
    k_nodes<<<(NSEL + 255) / 256, 256>>>(u_id, pos, neg);

    // layer-0 slice of the output (unnormalized E0)
    k_gather<<<(NSEL * 32 + 255) / 256, 256>>>(u_id, pos, neg, out, 0);

    // Full layers 0,1 (their outputs feed the next SpMM over all nodes)
    for (int l = 0; l < NLAYER - 1; l++) {
        k_spmm<<<2048, 256>>>();
        k_gemm<<<(N_NODES_ + GBM - 1) / GBM, GT>>>(W1 + (size_t)l * EMB * EMB, b1 + l * EMB,
                                                   W2 + (size_t)l * EMB * EMB, b2 + l * EMB);
        k_gather<<<(NSEL * 32 + 255) / 256, 256>>>(u_id, pos, neg, out, l + 1);
    }

    // Final layer: only the 12288 selected rows are ever read.
    {
        int l = NLAYER - 1;
        k_spmm_sel<<<(NSEL * 32 + 255) / 256, 256>>>();
        k_gemm_sel<<<NSEL / GBM, GT>>>(W1 + (size_t)l * EMB * EMB, b1 + l * EMB,
                                       W2 + (size_t)l * EMB * EMB, b2 + l * EMB);
        k_gather_sel<<<(NSEL * 32 + 255) / 256, 256>>>(out, NLAYER);
    }
}

// round 12
// speedup vs baseline: 3.5252x; 1.8797x over previous
#include <cuda_runtime.h>

#define N_USER   200000
#define N_ITEM   100000
#define N_NODES_ 300000
#define EMB      80
#define EMBV     20          // float4 chunks per row
#define FEAT     16
#define NNZ_     1000000
#define BATCH_   4096
#define NSEL     (3 * BATCH_)   // 12288 selected rows
#define NLAYER   3

// ---------------- device scratch ----------------
static __device__ float g_E [(size_t)N_NODES_ * EMB];   // 96 MB
static __device__ float g_LE[(size_t)N_NODES_ * EMB];   // 96 MB
static __device__ float g_LEsel[(size_t)NSEL * EMB];    // 3.9 MB (entry-indexed)
static __device__ float g_Esel [(size_t)NSEL * EMB];    // 3.9 MB (entry-indexed)
static __device__ int   g_nodes[NSEL];
static __device__ int   g_rowptr[N_NODES_ + 1];
static __device__ int   g_cnt[N_NODES_];
static __device__ int   g_bsum[1024];
static __device__ int   g_winner[N_USER];
static __device__ int   g_cols[NNZ_];
static __device__ float g_vals[NNZ_];
// frontier sets
static __device__ int   g_flag1[N_NODES_];
static __device__ int   g_flag2[N_NODES_];
static __device__ int   g_list1[N_NODES_];
static __device__ int   g_list2[N_NODES_];
static __device__ int   g_n1;
static __device__ int   g_n2;

// ---------------- CSR build ----------------
__global__ void k_init() {
    int i = blockIdx.x * blockDim.x + threadIdx.x;
    if (i < N_NODES_) {
        g_cnt[i]   = 0;
        g_flag1[i] = 0;
        g_flag2[i] = 0;
    }
    if (i < N_USER) g_winner[i] = -1;
    if (i == 0) { g_n1 = 0; g_n2 = 0; }
}

__global__ void k_hist(const int* __restrict__ rows) {
    int i = blockIdx.x * blockDim.x + threadIdx.x;
    if (i < NNZ_) atomicAdd(&g_cnt[rows[i]], 1);
}

__global__ void k_scan1() {
    __shared__ int s[1024];
    int tid = threadIdx.x;
    int i = blockIdx.x * 1024 + tid;
    int v = (i < N_NODES_) ? g_cnt[i] : 0;
    s[tid] = v; __syncthreads();
    for (int off = 1; off < 1024; off <<= 1) {
        int t = (tid >= off) ? s[tid - off] : 0;
        __syncthreads();
        s[tid] += t;
        __syncthreads();
    }
    if (i < N_NODES_) g_rowptr[i] = s[tid] - v;
    if (tid == 1023) g_bsum[blockIdx.x] = s[1023];
}

__global__ void k_scan2(int nb) {
    __shared__ int s[1024];
    int tid = threadIdx.x;
    int v = (tid < nb) ? g_bsum[tid] : 0;
    s[tid] = v; __syncthreads();
    for (int off = 1; off < 1024; off <<= 1) {
        int t = (tid >= off) ? s[tid - off] : 0;
        __syncthreads();
        s[tid] += t;
        __syncthreads();
    }
    if (tid < nb) g_bsum[tid] = s[tid] - v;
}

__global__ void k_scan3() {
    int i = blockIdx.x * blockDim.x + threadIdx.x;
    if (i < N_NODES_) {
        int excl = g_rowptr[i] + g_bsum[i >> 10];
        g_rowptr[i] = excl;
        g_cnt[i]    = excl;
    }
    if (i == 0) g_rowptr[N_NODES_] = NNZ_;
}

__global__ void k_scatter(const int* __restrict__ rows, const int* __restrict__ cols,
                          const float* __restrict__ vals) {
    int i = blockIdx.x * blockDim.x + threadIdx.x;
    if (i < NNZ_) {
        int p = atomicAdd(&g_cnt[rows[i]], 1);
        g_cols[p] = cols[i];
        g_vals[p] = vals[i];
    }
}

// ---------------- E init + blend scatter + node list ----------------
__global__ void k_init_E(const float4* __restrict__ user_tab, const float4* __restrict__ item_tab) {
    int i = blockIdx.x * blockDim.x + threadIdx.x;
    const int tot_u = N_USER * EMBV;
    const int tot   = N_NODES_ * EMBV;
    if (i < tot_u)      ((float4*)g_E)[i] = user_tab[i];
    else if (i < tot)   ((float4*)g_E)[i] = item_tab[i - tot_u];
}

__global__ void k_winner(const int* __restrict__ u_id) {
    int i = blockIdx.x * blockDim.x + threadIdx.x;
    if (i < BATCH_) atomicMax(&g_winner[u_id[i]], i);
}

__global__ void k_blend(const int* __restrict__ u_id, const int* __restrict__ age,
                        const int* __restrict__ sex, const int* __restrict__ month,
                        const int* __restrict__ day, const int* __restrict__ dow,
                        const float* __restrict__ user_tab,
                        const float* __restrict__ age_tab, const float* __restrict__ sex_tab,
                        const float* __restrict__ month_tab, const float* __restrict__ day_tab,
                        const float* __restrict__ dow_tab) {
    int i = blockIdx.x * blockDim.x + threadIdx.x;
    if (i >= BATCH_) return;
    int u = u_id[i];
    if (g_winner[u] != i) return;   // last occurrence wins
    float*       dst = g_E + (size_t)u * EMB;
    const float* src = user_tab + (size_t)u * EMB;
    const float* t0 = age_tab   + age[i]   * FEAT;
    const float* t1 = sex_tab   + sex[i]   * FEAT;
    const float* t2 = month_tab + month[i] * FEAT;
    const float* t3 = day_tab   + day[i]   * FEAT;
    const float* t4 = dow_tab   + dow[i]   * FEAT;
    #pragma unroll
    for (int j = 0; j < FEAT; j++) {
        dst[0*FEAT+j] = 0.5f * (src[0*FEAT+j] + t0[j]);
        dst[1*FEAT+j] = 0.5f * (src[1*FEAT+j] + t1[j]);
        dst[2*FEAT+j] = 0.5f * (src[2*FEAT+j] + t2[j]);
        dst[3*FEAT+j] = 0.5f * (src[3*FEAT+j] + t3[j]);
        dst[4*FEAT+j] = 0.5f * (src[4*FEAT+j] + t4[j]);
    }
}

__global__ void k_nodes(const int* __restrict__ u_id, const int* __restrict__ pos,
                        const int* __restrict__ neg) {
    int i = blockIdx.x * blockDim.x + threadIdx.x;
    if (i >= NSEL) return;
    int node;
    if (i < BATCH_)          node = u_id[i];
    else if (i < 2 * BATCH_) node = N_USER + pos[i - BATCH_];
    else                     node = N_USER + neg[i - 2 * BATCH_];
    g_nodes[i] = node;
}

// ---------------- frontier set construction ----------------
// S1 = Ssel ∪ N(Ssel)   (rows where E2 is read)
__global__ void k_mark_sel() {
    int w    = (blockIdx.x * blockDim.x + threadIdx.x) >> 5;
    int lane = threadIdx.x & 31;
    if (w >= NSEL) return;
    int row = g_nodes[w];
    if (lane == 0) g_flag1[row] = 1;
    int s = g_rowptr[row], e = g_rowptr[row + 1];
    for (int i = s + lane; i < e; i += 32) g_flag1[g_cols[i]] = 1;
}

__global__ void k_compact1() {
    int i = blockIdx.x * blockDim.x + threadIdx.x;
    if (i < N_NODES_ && g_flag1[i]) {
        int p = atomicAdd(&g_n1, 1);
        g_list1[p] = i;
    }
}

// S2 = S1 ∪ N(S1)   (rows where E1 is read)
__global__ void k_mark_list() {
    int n    = g_n1;
    int w0   = (blockIdx.x * blockDim.x + threadIdx.x) >> 5;
    int lane = threadIdx.x & 31;
    int nw   = (gridDim.x * blockDim.x) >> 5;
    for (int idx = w0; idx < n; idx += nw) {
        int row = g_list1[idx];
        if (lane == 0) g_flag2[row] = 1;
        int s = g_rowptr[row], e = g_rowptr[row + 1];
        for (int i = s + lane; i < e; i += 32) g_flag2[g_cols[i]] = 1;
    }
}

__global__ void k_compact2() {
    int i = blockIdx.x * blockDim.x + threadIdx.x;
    if (i < N_NODES_ && g_flag2[i]) {
        int p = atomicAdd(&g_n2, 1);
        g_list2[p] = i;
    }
}

// ---------------- SpMM over a row list (node-indexed output) ----------------
__global__ void k_spmm_l(int which) {
    int n           = which ? g_n1 : g_n2;
    const int* list = which ? g_list1 : g_list2;
    int gw   = (blockIdx.x * blockDim.x + threadIdx.x) >> 5;
    int lane = threadIdx.x & 31;
    int nw   = (gridDim.x * blockDim.x) >> 5;
    const float4* E4 = (const float4*)g_E;
    float4*       L4 = (float4*)g_LE;
    for (int idx = gw; idx < n; idx += nw) {
        int row = list[idx];
        int s = g_rowptr[row], e = g_rowptr[row + 1];
        if (lane < EMBV) {
            float4 acc = make_float4(0.f, 0.f, 0.f, 0.f);
            for (int i = s; i < e; i++) {
                float v = g_vals[i];
                int   c = g_cols[i];
                float4 x = __ldg(&E4[(size_t)c * EMBV + lane]);
                acc.x = fmaf(v, x.x, acc.x);
                acc.y = fmaf(v, x.y, acc.y);
                acc.z = fmaf(v, x.z, acc.z);
                acc.w = fmaf(v, x.w, acc.w);
            }
            L4[(size_t)row * EMBV + lane] = acc;
        }
    }
}

// Selective SpMM for final layer (entry-indexed output)
__global__ void k_spmm_sel() {
    int gw   = (blockIdx.x * blockDim.x + threadIdx.x) >> 5;
    int lane = threadIdx.x & 31;
    if (gw >= NSEL) return;
    int row = g_nodes[gw];
    const float4* E4 = (const float4*)g_E;
    float4*       L4 = (float4*)g_LEsel;
    int s = g_rowptr[row], e = g_rowptr[row + 1];
    if (lane < EMBV) {
        float4 acc = make_float4(0.f, 0.f, 0.f, 0.f);
        for (int i = s; i < e; i++) {
            float v = g_vals[i];
            int   c = g_cols[i];
            float4 x = __ldg(&E4[(size_t)c * EMBV + lane]);
            acc.x = fmaf(v, x.x, acc.x);
            acc.y = fmaf(v, x.y, acc.y);
            acc.z = fmaf(v, x.z, acc.z);
            acc.w = fmaf(v, x.w, acc.w);
        }
        L4[(size_t)gw * EMBV + lane] = acc;
    }
}

// ---------------- GEMM + bias + leaky (proven round-1 scalar core) ----------------
#define GBM 64
#define GT  160
#define XS  164   // padded row stride (floats)

__device__ __forceinline__ void fma4(float4& a, float s, const float4 w) {
    a.x = fmaf(s, w.x, a.x);
    a.y = fmaf(s, w.y, a.y);
    a.z = fmaf(s, w.z, a.z);
    a.w = fmaf(s, w.w, a.w);
}

// X tile staged in Xs; computes acc + epilogue. list==nullptr → direct row index.
__device__ __forceinline__ void gemm_core_epilogue(
        const float* Xs, const float* Bs, int tid,
        const float* __restrict__ W1l, const float* __restrict__ W2l,
        float4* __restrict__ out4, const int* __restrict__ list,
        int row0, int row_limit) {
    int tx = tid % EMBV;        // col chunk (float4), 0..19
    int ty = tid / EMBV;        // row group, 0..7 (8 rows each)

    float4 acc[8];
    #pragma unroll
    for (int r = 0; r < 8; r++) acc[r] = make_float4(0.f, 0.f, 0.f, 0.f);

    const float4* W14 = (const float4*)W1l;   // [80][20] float4
    const float4* W24 = (const float4*)W2l;
    const float*  xb  = Xs + (ty * 8) * XS;

    for (int k = 0; k < EMB; k += 4) {
        float4 w0 = __ldg(&W14[(k + 0) * EMBV + tx]);
        float4 w1 = __ldg(&W14[(k + 1) * EMBV + tx]);
        float4 w2 = __ldg(&W14[(k + 2) * EMBV + tx]);
        float4 w3 = __ldg(&W14[(k + 3) * EMBV + tx]);
        #pragma unroll
        for (int r = 0; r < 8; r++) {
            float4 xv = *(const float4*)(xb + r * XS + k);
            fma4(acc[r], xv.x, w0);
            fma4(acc[r], xv.y, w1);
            fma4(acc[r], xv.z, w2);
            fma4(acc[r], xv.w, w3);
        }
    }
    for (int k = 0; k < EMB; k += 4) {
        float4 w0 = __ldg(&W24[(k + 0) * EMBV + tx]);
        float4 w1 = __ldg(&W24[(k + 1) * EMBV + tx]);
        float4 w2 = __ldg(&W24[(k + 2) * EMBV + tx]);
        float4 w3 = __ldg(&W24[(k + 3) * EMBV + tx]);
        #pragma unroll
        for (int r = 0; r < 8; r++) {
            float4 xv = *(const float4*)(xb + r * XS + EMB + k);
            fma4(acc[r], xv.x, w0);
            fma4(acc[r], xv.y, w1);
            fma4(acc[r], xv.z, w2);
            fma4(acc[r], xv.w, w3);
        }
    }

    float4 b = ((const float4*)Bs)[tx];
    #pragma unroll
    for (int r = 0; r < 8; r++) {
        int gr = row0 + ty * 8 + r;
        if (gr < row_limit) {
            float4 v;
            v.x = acc[r].x + b.x;
            v.y = acc[r].y + b.y;
            v.z = acc[r].z + b.z;
            v.w = acc[r].w + b.w;
            v.x = (v.x > 0.f) ? v.x : 0.2f * v.x;
            v.y = (v.y > 0.f) ? v.y : 0.2f * v.y;
            v.z = (v.z > 0.f) ? v.z : 0.2f * v.z;
            v.w = (v.w > 0.f) ? v.w : 0.2f * v.w;
            int orow = list ? list[gr] : gr;
            out4[(size_t)orow * EMBV + tx] = v;
        }
    }
}

// List-driven GEMM: 64 list entries per block; node-indexed in-place E update.
__global__ __launch_bounds__(GT) void k_gemm_l(int which,
                                               const float* __restrict__ W1l,
                                               const float* __restrict__ b1l,
                                               const float* __restrict__ W2l,
                                               const float* __restrict__ b2l) {
    __shared__ float Xs[GBM * XS];   // 41.98 KB
    __shared__ float Bs[EMB];

    int n           = which ? g_n1 : g_n2;
    const int* list = which ? g_list1 : g_list2;
    int tid  = threadIdx.x;
    int row0 = blockIdx.x * GBM;
    if (row0 >= n) return;          // uniform across block (before any sync)

    if (tid < EMB) Bs[tid] = 2.0f * b1l[tid] + b2l[tid];

    const float4* E4 = (const float4*)g_E;
    const float4* L4 = (const float4*)g_LE;
    for (int j = tid; j < GBM * EMBV; j += GT) {
        int r = j / EMBV, c = j % EMBV;
        int idx = row0 + r;
        float4 le = make_float4(0.f, 0.f, 0.f, 0.f), e = le;
        if (idx < n) {
            int node = list[idx];
            le = L4[(size_t)node * EMBV + c];
            e  = E4[(size_t)node * EMBV + c];
        }
        float4* xr = (float4*)(Xs + r * XS);
        xr[c]        = make_float4(le.x + e.x, le.y + e.y, le.z + e.z, le.w + e.w);
        xr[EMBV + c] = make_float4(le.x * e.x, le.y * e.y, le.z * e.z, le.w * e.w);
    }
    __syncthreads();

    gemm_core_epilogue(Xs, Bs, tid, W1l, W2l, (float4*)g_E, list, row0, n);
}

// Selective GEMM (final layer): entry-indexed LE/output.
__global__ __launch_bounds__(GT) void k_gemm_sel(const float* __restrict__ W1l,
                                                 const float* __restrict__ b1l,
                                                 const float* __restrict__ W2l,
                                                 const float* __restrict__ b2l) {
    __shared__ float Xs[GBM * XS];
    __shared__ float Bs[EMB];

    int tid  = threadIdx.x;
    int row0 = blockIdx.x * GBM;   // NSEL = 192*64 exact

    if (tid < EMB) Bs[tid] = 2.0f * b1l[tid] + b2l[tid];

    const float4* E4 = (const float4*)g_E;
    const float4* L4 = (const float4*)g_LEsel;
    for (int j = tid; j < GBM * EMBV; j += GT) {
        int r = j / EMBV, c = j % EMBV;
        int entry = row0 + r;
        int node  = g_nodes[entry];
        float4 le = L4[(size_t)entry * EMBV + c];
        float4 e  = E4[(size_t)node  * EMBV + c];
        float4* xr = (float4*)(Xs + r * XS);
        xr[c]        = make_float4(le.x + e.x, le.y + e.y, le.z + e.z, le.w + e.w);
        xr[EMBV + c] = make_float4(le.x * e.x, le.y * e.y, le.z * e.z, le.w * e.w);
    }
    __syncthreads();

    gemm_core_epilogue(Xs, Bs, tid, W1l, W2l, (float4*)g_Esel, nullptr, row0, NSEL);
}

// ---------------- gather + row-normalize selected rows into output ----------------
__global__ void k_gather(const int* __restrict__ u_id, const int* __restrict__ pos,
                         const int* __restrict__ neg, float* __restrict__ out, int layer) {
    int gw   = (blockIdx.x * blockDim.x + threadIdx.x) >> 5;
    int lane = threadIdx.x & 31;
    if (gw >= NSEL) return;
    int node;
    if (gw < BATCH_)          node = u_id[gw];
    else if (gw < 2 * BATCH_) node = N_USER + pos[gw - BATCH_];
    else                      node = N_USER + neg[gw - 2 * BATCH_];

    const float4* E4 = (const float4*)g_E;
    float4 v = make_float4(0.f, 0.f, 0.f, 0.f);
    if (lane < EMBV) v = E4[(size_t)node * EMBV + lane];
    float ss = v.x * v.x + v.y * v.y + v.z * v.z + v.w * v.w;
    #pragma unroll
    for (int o = 16; o; o >>= 1) ss += __shfl_xor_sync(0xffffffffu, ss, o);
    float scale = 1.0f;
    if (layer > 0) scale = 1.0f / fmaxf(sqrtf(ss), 1e-12f);
    if (lane < EMBV) {
        float4 r = make_float4(v.x * scale, v.y * scale, v.z * scale, v.w * scale);
        ((float4*)(out + (size_t)gw * (4 * EMB) + layer * EMB))[lane] = r;
    }
}

__global__ void k_gather_sel(float* __restrict__ out, int layer) {
    int gw   = (blockIdx.x * blockDim.x + threadIdx.x) >> 5;
    int lane = threadIdx.x & 31;
    if (gw >= NSEL) return;
    const float4* E4 = (const float4*)g_Esel;
    float4 v = make_float4(0.f, 0.f, 0.f, 0.f);
    if (lane < EMBV) v = E4[(size_t)gw * EMBV + lane];
    float ss = v.x * v.x + v.y * v.y + v.z * v.z + v.w * v.w;
    #pragma unroll
    for (int o = 16; o; o >>= 1) ss += __shfl_xor_sync(0xffffffffu, ss, o);
    float scale = 1.0f / fmaxf(sqrtf(ss), 1e-12f);
    if (lane < EMBV) {
        float4 r = make_float4(v.x * scale, v.y * scale, v.z * scale, v.w * scale);
        ((float4*)(out + (size_t)gw * (4 * EMB) + layer * EMB))[lane] = r;
    }
}

// ---------------- launch ----------------
extern "C" void kernel_launch(void* const* d_in, const int* in_sizes, int n_in,
                              void* d_out, int out_size) {
    const int*   u_id      = (const int*)d_in[0];
    const int*   age       = (const int*)d_in[1];
    const int*   sex       = (const int*)d_in[2];
    const int*   month     = (const int*)d_in[3];
    const int*   day       = (const int*)d_in[4];
    const int*   dow       = (const int*)d_in[5];
    const int*   pos       = (const int*)d_in[6];
    const int*   neg       = (const int*)d_in[7];
    const int*   lrows     = (const int*)d_in[8];
    const int*   lcols     = (const int*)d_in[9];
    const float* lvals     = (const float*)d_in[10];
    const float* user_tab  = (const float*)d_in[11];
    const float* item_tab  = (const float*)d_in[12];
    const float* age_tab   = (const float*)d_in[13];
    const float* sex_tab   = (const float*)d_in[14];
    const float* month_tab = (const float*)d_in[15];
    const float* day_tab   = (const float*)d_in[16];
    const float* dow_tab   = (const float*)d_in[17];
    const float* W1        = (const float*)d_in[18];
    const float* b1        = (const float*)d_in[19];
    const float* W2        = (const float*)d_in[20];
    const float* b2        = (const float*)d_in[21];
    float* out = (float*)d_out;

    const int GMAX = (N_NODES_ + GBM - 1) / GBM;   // 4688 (early-exit on device count)

    // CSR build (reused by all 3 layers)
    k_init<<<(N_NODES_ + 255) / 256, 256>>>();
    k_hist<<<(NNZ_ + 255) / 256, 256>>>(lrows);
    int nb = (N_NODES_ + 1023) / 1024;
    k_scan1<<<nb, 1024>>>();
    k_scan2<<<1, 1024>>>(nb);
    k_scan3<<<(N_NODES_ + 255) / 256, 256>>>();
    k_scatter<<<(NNZ_ + 255) / 256, 256>>>(lrows, lcols, lvals);

    // E0 + node list
    k_init_E<<<(N_NODES_ * EMBV + 255) / 256, 256>>>((const float4*)user_tab,
                                                     (const float4*)item_tab);
    k_winner<<<(BATCH_ + 255) / 256, 256>>>(u_id);
    k_blend<<<(BATCH_ + 255) / 256, 256>>>(u_id, age, sex, month, day, dow, user_tab,
                                           age_tab, sex_tab, month_tab, day_tab, dow_tab);
    k_nodes<<<(NSEL + 255) / 256, 256>>>(u_id, pos, neg);

    // frontier sets: S1 = Ssel ∪ N(Ssel); S2 = S1 ∪ N(S1)
    k_mark_sel<<<(NSEL * 32 + 255) / 256, 256>>>();
    k_compact1<<<(N_NODES_ + 255) / 256, 256>>>();
    k_mark_list<<<1024, 256>>>();
    k_compact2<<<(N_NODES_ + 255) / 256, 256>>>();

    // layer-0 slice of the output (unnormalized E0)
    k_gather<<<(NSEL * 32 + 255) / 256, 256>>>(u_id, pos, neg, out, 0);

    // layer 0 over S2 (E1 only ever read at S2)
    k_spmm_l<<<2048, 256>>>(0);
    k_gemm_l<<<GMAX, GT>>>(0, W1, b1, W2, b2);
    k_gather<<<(NSEL * 32 + 255) / 256, 256>>>(u_id, pos, neg, out, 1);

    // layer 1 over S1 (E2 only ever read at S1)
    k_spmm_l<<<2048, 256>>>(1);
    k_gemm_l<<<GMAX, GT>>>(1, W1 + (size_t)EMB * EMB, b1 + EMB,
                              W2 + (size_t)EMB * EMB, b2 + EMB);
    k_gather<<<(NSEL * 32 + 255) / 256, 256>>>(u_id, pos, neg, out, 2);

    // layer 2: selective (entry-indexed)
    k_spmm_sel<<<(NSEL * 32 + 255) / 256, 256>>>();
    k_gemm_sel<<<NSEL / GBM, GT>>>(W1 + (size_t)2 * EMB * EMB, b1 + 2 * EMB,
                                   W2 + (size_t)2 * EMB * EMB, b2 + 2 * EMB);
    k_gather_sel<<<(NSEL * 32 + 255) / 256, 256>>>(out, NLAYER);
}